// round 12
// baseline (speedup 1.0000x reference)
#include <cuda_runtime.h>
#include <math.h>
#include <stdint.h>

#define DIM 768
#define TOK 4096          // B*N = 2*2048
#define SEQ 2048
#define NHEAD 12
#define HDIM 64
#define MLPD 3072

// ---------------- scratch (static device globals; no allocation) ----------------
__device__ float g_xn[TOK * DIM];
__device__ float g_qkv[TOK * 3 * DIM];
__device__ float g_attn[TOK * DIM];
__device__ float g_x1[TOK * DIM];
__device__ float g_h[TOK * DIM];
__device__ float g_h1[TOK * MLPD];
__device__ float g_part[4 * TOK * DIM];   // split-K partials (proj uses 2, lin2 uses 4)

// ---------------- LayerNorm: one block (256 thr) per row of 768 ----------------
__global__ void ln_kernel(const float* __restrict__ x, const float* __restrict__ w,
                          const float* __restrict__ b, float* __restrict__ y) {
    const int row = blockIdx.x;
    const int tid = threadIdx.x;
    const float* xr = x + (size_t)row * DIM;
    float v0 = xr[tid], v1 = xr[tid + 256], v2 = xr[tid + 512];
    float s  = v0 + v1 + v2;
    float sq = v0 * v0 + v1 * v1 + v2 * v2;
    __shared__ float red0[8], red1[8];
    #pragma unroll
    for (int mm = 16; mm; mm >>= 1) {
        s  += __shfl_xor_sync(0xffffffffu, s,  mm);
        sq += __shfl_xor_sync(0xffffffffu, sq, mm);
    }
    const int wid = tid >> 5, lane = tid & 31;
    if (lane == 0) { red0[wid] = s; red1[wid] = sq; }
    __syncthreads();
    if (wid == 0) {
        s = red0[lane & 7]; sq = red1[lane & 7];
        #pragma unroll
        for (int mm = 4; mm; mm >>= 1) {
            s  += __shfl_xor_sync(0xffffffffu, s,  mm);
            sq += __shfl_xor_sync(0xffffffffu, sq, mm);
        }
        if (lane == 0) { red0[0] = s; red1[0] = sq; }
    }
    __syncthreads();
    s = red0[0]; sq = red1[0];
    const float mu  = s * (1.0f / DIM);
    const float var = sq * (1.0f / DIM) - mu * mu;
    const float r   = rsqrtf(var + 1e-5f);
    float* yr = y + (size_t)row * DIM;
    yr[tid]       = (v0 - mu) * r * w[tid]       + b[tid];
    yr[tid + 256] = (v1 - mu) * r * w[tid + 256] + b[tid + 256];
    yr[tid + 512] = (v2 - mu) * r * w[tid + 512] + b[tid + 512];
}

// ---------------- tf32 helpers ----------------
__device__ __forceinline__ uint32_t f2tf32(float f) {
    uint32_t u;
    asm("cvt.rna.tf32.f32 %0, %1;" : "=r"(u) : "f"(f));
    return u;
}

__device__ __forceinline__ void mma_tf32(float& c0, float& c1, float& c2, float& c3,
                                         uint32_t a0, uint32_t a1, uint32_t a2, uint32_t a3,
                                         uint32_t b0, uint32_t b1) {
    asm volatile(
        "mma.sync.aligned.m16n8k8.row.col.f32.tf32.tf32.f32 "
        "{%0,%1,%2,%3}, {%4,%5,%6,%7}, {%8,%9}, {%0,%1,%2,%3};"
        : "+f"(c0), "+f"(c1), "+f"(c2), "+f"(c3)
        : "r"(a0), "r"(a1), "r"(a2), "r"(a3), "r"(b0), "r"(b1));
}

// ---------------- cp.async helpers ----------------
__device__ __forceinline__ void cp16(uint32_t smem_addr, const void* gptr) {
    asm volatile("cp.async.cg.shared.global [%0], [%1], 16;" :: "r"(smem_addr), "l"(gptr));
}
__device__ __forceinline__ void cp_commit() {
    asm volatile("cp.async.commit_group;" ::: "memory");
}
template <int N>
__device__ __forceinline__ void cp_wait() {
    asm volatile("cp.async.wait_group %0;" :: "n"(N) : "memory");
}
__device__ __forceinline__ uint32_t smem_u32(const void* p) {
    uint32_t a;
    asm("{ .reg .u64 t; cvta.to.shared.u64 t, %1; cvt.u32.u64 %0, t; }" : "=r"(a) : "l"(p));
    return a;
}

// ---------------- tf32 GEMM 128x128, BK=16, 4-stage cp.async pipeline ----------------
// Raw smem layouts (padded for conflict-free fragment reads):
//   A stage: [128][20] row-major (m, k)   -- reads 20g+tig distinct mod 32
//   B stage: [16][136] row-major (k, n)   -- reads 8*tig+g distinct mod 32
// cvt.rna applied at fragment read (numerically == cvt-at-write).
// K = row stride of A; klen = K-extent this launch; blockIdx.z = split-K slice.
// EPI: 0 = bias, 1 = bias + residual, 2 = bias + exact GELU, 3 = raw partial
#define AP_STRIDE 20
#define BP_STRIDE 136
#define A_STAGE (128 * AP_STRIDE)            // 2560 floats
#define B_STAGE (16 * BP_STRIDE)             // 2176 floats
#define TG_SMEM_FLOATS (4 * A_STAGE + 4 * B_STAGE)
#define TG_SMEM_BYTES (TG_SMEM_FLOATS * 4)   // 75776 B

template <int EPI>
__global__ __launch_bounds__(256, 2)
void tgemm_kernel(const float* __restrict__ A, const float* __restrict__ W,
                  const float* __restrict__ bias, const float* __restrict__ res,
                  float* __restrict__ C, int M, int N, int K, int klen) {
    extern __shared__ float dyn[];
    float* Asm = dyn;                         // 4 stages x A_STAGE
    float* Bsm = dyn + 4 * A_STAGE;           // 4 stages x B_STAGE

    const int tid = threadIdx.x;
    const int bm = blockIdx.y * 128, bn = blockIdx.x * 128;
    const int z = blockIdx.z;
    A += (size_t)z * klen;
    W += (size_t)z * klen * N;
    if (EPI == 3) C += (size_t)z * M * N;

    const int wid = tid >> 5, lane = tid & 31;
    const int warp_m = wid & 1, warp_n = wid >> 1;       // 2 x 4
    const int g = lane >> 2, tig = lane & 3;

    // global copy coverage (per thread: 2x16B from A, 2x16B from B per stage)
    const int ar = tid >> 2, ac4 = tid & 3;              // A rows ar, ar+64; k-off ac4*4
    const int brr = tid >> 5;                             // B k-rows brr, brr+8
    const int bcg = (tid & 31) * 4;                       // B n-cols bcg..+3
    const float* ApG  = A + (size_t)(bm + ar) * K + ac4 * 4;
    const float* ApG2 = ApG + (size_t)64 * K;
    const float* BpG  = W + (size_t)brr * N + bn + bcg;
    const float* BpG2 = BpG + (size_t)8 * N;

    const uint32_t sb = smem_u32(dyn);
    const uint32_t adst0 = sb + (ar * AP_STRIDE + ac4 * 4) * 4;
    const uint32_t adst1 = sb + ((ar + 64) * AP_STRIDE + ac4 * 4) * 4;
    const uint32_t bbase = sb + 4 * A_STAGE * 4;
    const uint32_t bdst0 = bbase + (brr * BP_STRIDE + bcg) * 4;
    const uint32_t bdst1 = bbase + ((brr + 8) * BP_STRIDE + bcg) * 4;

    const int nk = klen >> 4;                             // BK = 16

    // stage issue: copies for k-tile `ktile` into stage slot `s`
    auto stage_copy = [&](int s, int ktile) {
        if (ktile < nk) {
            const uint32_t ao = (uint32_t)(s * A_STAGE * 4);
            const uint32_t bo = (uint32_t)(s * B_STAGE * 4);
            cp16(adst0 + ao, ApG  + ktile * 16);
            cp16(adst1 + ao, ApG2 + ktile * 16);
            cp16(bdst0 + bo, BpG  + (size_t)ktile * 16 * N);
            cp16(bdst1 + bo, BpG2 + (size_t)ktile * 16 * N);
        }
        cp_commit();
    };

    float acc[4][4][4];
    #pragma unroll
    for (int i = 0; i < 4; ++i)
        #pragma unroll
        for (int j = 0; j < 4; ++j)
            #pragma unroll
            for (int c = 0; c < 4; ++c) acc[i][j][c] = 0.0f;

    // prologue: fill 3 stages
    stage_copy(0, 0);
    stage_copy(1, 1);
    stage_copy(2, 2);

    for (int kt = 0; kt < nk; ++kt) {
        cp_wait<2>();          // stage kt's group complete (this thread)
        __syncthreads();       // all threads' copies visible; prev reads of (kt+3)&3 done

        stage_copy((kt + 3) & 3, kt + 3);   // refill oldest slot

        const float* As = Asm + (kt & 3) * A_STAGE;
        const float* Bs = Bsm + (kt & 3) * B_STAGE;

        #pragma unroll
        for (int ks8 = 0; ks8 < 2; ++ks8) {
            const int ko = ks8 * 8;
            uint32_t bfr[4][2];
            #pragma unroll
            for (int j = 0; j < 4; ++j) {
                const int nb = warp_n * 32 + j * 8 + g;
                bfr[j][0] = f2tf32(Bs[(ko + tig) * BP_STRIDE + nb]);
                bfr[j][1] = f2tf32(Bs[(ko + tig + 4) * BP_STRIDE + nb]);
            }
            #pragma unroll
            for (int i = 0; i < 4; ++i) {
                const int mb = warp_m * 64 + i * 16;
                const uint32_t a0 = f2tf32(As[(mb + g) * AP_STRIDE + ko + tig]);
                const uint32_t a1 = f2tf32(As[(mb + g + 8) * AP_STRIDE + ko + tig]);
                const uint32_t a2 = f2tf32(As[(mb + g) * AP_STRIDE + ko + tig + 4]);
                const uint32_t a3 = f2tf32(As[(mb + g + 8) * AP_STRIDE + ko + tig + 4]);
                #pragma unroll
                for (int j = 0; j < 4; ++j)
                    mma_tf32(acc[i][j][0], acc[i][j][1], acc[i][j][2], acc[i][j][3],
                             a0, a1, a2, a3, bfr[j][0], bfr[j][1]);
            }
        }
    }

    // ---- epilogue: thread owns rows {g, g+8} per m-tile, col pair 2*tig per n-tile
    #pragma unroll
    for (int i = 0; i < 4; ++i) {
        #pragma unroll
        for (int half = 0; half < 2; ++half) {
            const int r = bm + warp_m * 64 + i * 16 + g + half * 8;
            float* Crow = C + (size_t)r * N;
            const float* Rrow = (EPI == 1) ? (res + (size_t)r * N) : nullptr;
            #pragma unroll
            for (int j = 0; j < 4; ++j) {
                const int col = bn + warp_n * 32 + j * 8 + tig * 2;
                float v0 = acc[i][j][half * 2 + 0];
                float v1 = acc[i][j][half * 2 + 1];
                if (EPI != 3) { v0 += bias[col]; v1 += bias[col + 1]; }
                if (EPI == 1) {
                    v0 += Rrow[col];
                    v1 += Rrow[col + 1];
                }
                if (EPI == 2) {
                    v0 = 0.5f * v0 * (1.0f + erff(v0 * 0.70710678118654752f));
                    v1 = 0.5f * v1 * (1.0f + erff(v1 * 0.70710678118654752f));
                }
                *(float2*)&Crow[col] = make_float2(v0, v1);
            }
        }
    }
}

// ---------------- split-K combines ----------------
// proj: x1 = x + bias + p0 + p1
__global__ void combine2_kernel(const float* __restrict__ p, const float* __restrict__ x,
                                const float* __restrict__ bias, float* __restrict__ out) {
    const int i = (blockIdx.x * 256 + threadIdx.x) * 4;
    const int col = i % DIM;
    float4 a = *(const float4*)&p[i];
    float4 b = *(const float4*)&p[(size_t)TOK * DIM + i];
    float4 r = *(const float4*)&x[i];
    float4 bb = *(const float4*)&bias[col];
    float4 o;
    o.x = r.x + bb.x + a.x + b.x;
    o.y = r.y + bb.y + a.y + b.y;
    o.z = r.z + bb.z + a.z + b.z;
    o.w = r.w + bb.w + a.w + b.w;
    *(float4*)&out[i] = o;
}

// lin2: out = x1 + bias + p0 + p1 + p2 + p3
__global__ void combine4_kernel(const float* __restrict__ p, const float* __restrict__ x1,
                                const float* __restrict__ bias, float* __restrict__ out) {
    const int i = (blockIdx.x * 256 + threadIdx.x) * 4;
    const int col = i % DIM;
    float4 a = *(const float4*)&p[i];
    float4 b = *(const float4*)&p[(size_t)TOK * DIM + i];
    float4 c = *(const float4*)&p[(size_t)2 * TOK * DIM + i];
    float4 d = *(const float4*)&p[(size_t)3 * TOK * DIM + i];
    float4 r = *(const float4*)&x1[i];
    float4 bb = *(const float4*)&bias[col];
    float4 o;
    o.x = r.x + bb.x + ((a.x + b.x) + (c.x + d.x));
    o.y = r.y + bb.y + ((a.y + b.y) + (c.y + d.y));
    o.z = r.z + bb.z + ((a.z + b.z) + (c.z + d.z));
    o.w = r.w + bb.w + ((a.w + b.w) + (c.w + d.w));
    *(float4*)&out[i] = o;
}

// ---------------- tf32 tensor-core flash attention ----------------
// P aliased into K's buffer -> smem 53.2KB -> 4 CTAs/SM. cvt.rna at staging.
#define QP 68
#define VP 72
#define FLASH_SMEM_U32 (64 * QP /*Q*/ + 64 * QP /*K=P*/ + 64 * VP /*V*/)

__global__ __launch_bounds__(128, 4)
void flash_tc_kernel(const float* __restrict__ qkv, float* __restrict__ out) {
    extern __shared__ uint32_t sm[];
    uint32_t* Qs = sm;                 // 64 x QP
    uint32_t* Ks = Qs + 64 * QP;       // 64 x QP  (becomes P after S-compute)
    uint32_t* Vs = Ks + 64 * QP;       // 64 x VP
    uint32_t* Ps = Ks;                 // alias

    const int tid = threadIdx.x;
    const int wid = tid >> 5, lane = tid & 31;
    const int g = lane >> 2, tig = lane & 3;
    const int bh = blockIdx.y;
    const int b = bh / NHEAD, h = bh % NHEAD;
    const int q0 = blockIdx.x * 64;
    const int r0 = wid * 16;
    const size_t base = (size_t)b * SEQ * (3 * DIM);

    #pragma unroll
    for (int it = 0; it < 8; ++it) {
        const int f = tid + it * 128;
        const int row = f >> 4, c4 = f & 15;
        float4 q = *(const float4*)&qkv[base + (size_t)(q0 + row) * (3 * DIM) + h * 64 + c4 * 4];
        uint32_t* p = &Qs[row * QP + c4 * 4];
        p[0] = f2tf32(q.x); p[1] = f2tf32(q.y); p[2] = f2tf32(q.z); p[3] = f2tf32(q.w);
    }

    float m0 = -1e30f, m1 = -1e30f, l0 = 0.0f, l1 = 0.0f;
    float oacc[8][4];
    #pragma unroll
    for (int j = 0; j < 8; ++j)
        #pragma unroll
        for (int c = 0; c < 4; ++c) oacc[j][c] = 0.0f;

    for (int kt = 0; kt < SEQ / 64; ++kt) {
        __syncthreads();   // all warps done with P(=Ks) and Vs of previous iter
        #pragma unroll
        for (int it = 0; it < 8; ++it) {
            const int f = tid + it * 128;
            const int row = f >> 4, c4 = f & 15;
            const size_t off = base + (size_t)(kt * 64 + row) * (3 * DIM) + h * 64 + c4 * 4;
            float4 k = *(const float4*)&qkv[off + DIM];
            float4 v = *(const float4*)&qkv[off + 2 * DIM];
            uint32_t* pk = &Ks[row * QP + c4 * 4];
            pk[0] = f2tf32(k.x); pk[1] = f2tf32(k.y); pk[2] = f2tf32(k.z); pk[3] = f2tf32(k.w);
            uint32_t* pv = &Vs[row * VP + c4 * 4];
            pv[0] = f2tf32(v.x); pv[1] = f2tf32(v.y); pv[2] = f2tf32(v.z); pv[3] = f2tf32(v.w);
        }
        __syncthreads();

        float sacc[8][4];
        #pragma unroll
        for (int j = 0; j < 8; ++j)
            #pragma unroll
            for (int c = 0; c < 4; ++c) sacc[j][c] = 0.0f;

        #pragma unroll
        for (int ks = 0; ks < 64; ks += 8) {
            const uint32_t a0 = Qs[(r0 + g) * QP + ks + tig];
            const uint32_t a1 = Qs[(r0 + g + 8) * QP + ks + tig];
            const uint32_t a2 = Qs[(r0 + g) * QP + ks + tig + 4];
            const uint32_t a3 = Qs[(r0 + g + 8) * QP + ks + tig + 4];
            #pragma unroll
            for (int j = 0; j < 8; ++j) {
                const uint32_t b0 = Ks[(j * 8 + g) * QP + ks + tig];
                const uint32_t b1 = Ks[(j * 8 + g) * QP + ks + tig + 4];
                mma_tf32(sacc[j][0], sacc[j][1], sacc[j][2], sacc[j][3],
                         a0, a1, a2, a3, b0, b1);
            }
        }

        float rm0 = -1e30f, rm1 = -1e30f;
        #pragma unroll
        for (int j = 0; j < 8; ++j) {
            sacc[j][0] *= 0.125f; sacc[j][1] *= 0.125f;
            sacc[j][2] *= 0.125f; sacc[j][3] *= 0.125f;
            rm0 = fmaxf(rm0, fmaxf(sacc[j][0], sacc[j][1]));
            rm1 = fmaxf(rm1, fmaxf(sacc[j][2], sacc[j][3]));
        }
        rm0 = fmaxf(rm0, __shfl_xor_sync(0xffffffffu, rm0, 1));
        rm0 = fmaxf(rm0, __shfl_xor_sync(0xffffffffu, rm0, 2));
        rm1 = fmaxf(rm1, __shfl_xor_sync(0xffffffffu, rm1, 1));
        rm1 = fmaxf(rm1, __shfl_xor_sync(0xffffffffu, rm1, 2));

        const float mn0 = fmaxf(m0, rm0);
        const float mn1 = fmaxf(m1, rm1);
        const float alpha0 = __expf(m0 - mn0);
        const float alpha1 = __expf(m1 - mn1);
        m0 = mn0; m1 = mn1;

        float ps0 = 0.0f, ps1 = 0.0f;
        #pragma unroll
        for (int j = 0; j < 8; ++j) {
            sacc[j][0] = __expf(sacc[j][0] - mn0);
            sacc[j][1] = __expf(sacc[j][1] - mn0);
            sacc[j][2] = __expf(sacc[j][2] - mn1);
            sacc[j][3] = __expf(sacc[j][3] - mn1);
            ps0 += sacc[j][0] + sacc[j][1];
            ps1 += sacc[j][2] + sacc[j][3];
        }
        ps0 += __shfl_xor_sync(0xffffffffu, ps0, 1);
        ps0 += __shfl_xor_sync(0xffffffffu, ps0, 2);
        ps1 += __shfl_xor_sync(0xffffffffu, ps1, 1);
        ps1 += __shfl_xor_sync(0xffffffffu, ps1, 2);
        l0 = l0 * alpha0 + ps0;
        l1 = l1 * alpha1 + ps1;

        #pragma unroll
        for (int j = 0; j < 8; ++j) {
            oacc[j][0] *= alpha0; oacc[j][1] *= alpha0;
            oacc[j][2] *= alpha1; oacc[j][3] *= alpha1;
        }

        __syncthreads();   // all warps finished reading Ks before P overwrites it
        #pragma unroll
        for (int j = 0; j < 8; ++j) {
            const int col = j * 8 + 2 * tig;
            Ps[(r0 + g) * QP + col]         = f2tf32(sacc[j][0]);
            Ps[(r0 + g) * QP + col + 1]     = f2tf32(sacc[j][1]);
            Ps[(r0 + g + 8) * QP + col]     = f2tf32(sacc[j][2]);
            Ps[(r0 + g + 8) * QP + col + 1] = f2tf32(sacc[j][3]);
        }
        __syncwarp();      // P rows are warp-private; warp-local ordering suffices

        #pragma unroll
        for (int ks = 0; ks < 64; ks += 8) {
            const uint32_t a0 = Ps[(r0 + g) * QP + ks + tig];
            const uint32_t a1 = Ps[(r0 + g + 8) * QP + ks + tig];
            const uint32_t a2 = Ps[(r0 + g) * QP + ks + tig + 4];
            const uint32_t a3 = Ps[(r0 + g + 8) * QP + ks + tig + 4];
            #pragma unroll
            for (int j = 0; j < 8; ++j) {
                const uint32_t b0 = Vs[(ks + tig) * VP + j * 8 + g];
                const uint32_t b1 = Vs[(ks + tig + 4) * VP + j * 8 + g];
                mma_tf32(oacc[j][0], oacc[j][1], oacc[j][2], oacc[j][3],
                         a0, a1, a2, a3, b0, b1);
            }
        }
    }

    const float inv0 = 1.0f / l0;
    const float inv1 = 1.0f / l1;
    const int row_g  = b * SEQ + q0 + r0 + g;
    const int row_g8 = row_g + 8;
    #pragma unroll
    for (int j = 0; j < 8; ++j) {
        const int col = h * 64 + j * 8 + 2 * tig;
        *(float2*)&out[(size_t)row_g  * DIM + col] = make_float2(oacc[j][0] * inv0, oacc[j][1] * inv0);
        *(float2*)&out[(size_t)row_g8 * DIM + col] = make_float2(oacc[j][2] * inv1, oacc[j][3] * inv1);
    }
}

// ---------------- launch ----------------
static float* sym_addr(const void* sym) {
    void* p = nullptr;
    cudaGetSymbolAddress(&p, sym);
    return (float*)p;
}

extern "C" void kernel_launch(void* const* d_in, const int* in_sizes, int n_in,
                              void* d_out, int out_size) {
    const float* x     = (const float*)d_in[0];
    const float* ln1w  = (const float*)d_in[1];
    const float* ln1b  = (const float*)d_in[2];
    const float* qkvw  = (const float*)d_in[3];
    const float* qkvb  = (const float*)d_in[4];
    const float* projw = (const float*)d_in[5];
    const float* projb = (const float*)d_in[6];
    const float* ln2w  = (const float*)d_in[7];
    const float* ln2b  = (const float*)d_in[8];
    const float* lin1w = (const float*)d_in[9];
    const float* lin1b = (const float*)d_in[10];
    const float* lin2w = (const float*)d_in[11];
    const float* lin2b = (const float*)d_in[12];
    float* out = (float*)d_out;

    float* xn   = sym_addr(g_xn);
    float* qkvB = sym_addr(g_qkv);
    float* attn = sym_addr(g_attn);
    float* x1   = sym_addr(g_x1);
    float* hB   = sym_addr(g_h);
    float* h1   = sym_addr(g_h1);
    float* part = sym_addr(g_part);

    const int flash_smem = FLASH_SMEM_U32 * 4;
    cudaFuncSetAttribute(flash_tc_kernel, cudaFuncAttributeMaxDynamicSharedMemorySize, flash_smem);
    cudaFuncSetAttribute(tgemm_kernel<0>, cudaFuncAttributeMaxDynamicSharedMemorySize, TG_SMEM_BYTES);
    cudaFuncSetAttribute(tgemm_kernel<1>, cudaFuncAttributeMaxDynamicSharedMemorySize, TG_SMEM_BYTES);
    cudaFuncSetAttribute(tgemm_kernel<2>, cudaFuncAttributeMaxDynamicSharedMemorySize, TG_SMEM_BYTES);
    cudaFuncSetAttribute(tgemm_kernel<3>, cudaFuncAttributeMaxDynamicSharedMemorySize, TG_SMEM_BYTES);

    // 1. ln1
    ln_kernel<<<TOK, 256>>>(x, ln1w, ln1b, xn);
    // 2. qkv = xn @ qkv_w + b
    tgemm_kernel<0><<<dim3(3 * DIM / 128, TOK / 128, 1), 256, TG_SMEM_BYTES>>>(
        xn, qkvw, qkvb, nullptr, qkvB, TOK, 3 * DIM, DIM, DIM);
    // 3. attention (tf32 TC flash, 4 CTAs/SM)
    flash_tc_kernel<<<dim3(SEQ / 64, 2 * NHEAD), 128, flash_smem>>>(qkvB, attn);
    // 4a. proj partials (split-K=2)
    tgemm_kernel<3><<<dim3(DIM / 128, TOK / 128, 2), 256, TG_SMEM_BYTES>>>(
        attn, projw, nullptr, nullptr, part, TOK, DIM, DIM, DIM / 2);
    // 4b. x1 = x + proj_b + p0 + p1
    combine2_kernel<<<(TOK * DIM / 4) / 256, 256>>>(part, x, projb, x1);
    // 5. ln2
    ln_kernel<<<TOK, 256>>>(x1, ln2w, ln2b, hB);
    // 6. h1 = gelu(h @ lin1_w + b)
    tgemm_kernel<2><<<dim3(MLPD / 128, TOK / 128, 1), 256, TG_SMEM_BYTES>>>(
        hB, lin1w, lin1b, nullptr, h1, TOK, MLPD, DIM, DIM);
    // 7a. lin2 partials (split-K=4)
    tgemm_kernel<3><<<dim3(DIM / 128, TOK / 128, 4), 256, TG_SMEM_BYTES>>>(
        h1, lin2w, nullptr, nullptr, part, TOK, DIM, MLPD, MLPD / 4);
    // 7b. out = x1 + lin2_b + sum partials
    combine4_kernel<<<(TOK * DIM / 4) / 256, 256>>>(part, x1, lin2b, out);
}

// round 14
// speedup vs baseline: 1.0194x; 1.0194x over previous
#include <cuda_runtime.h>
#include <math.h>
#include <stdint.h>

#define DIM 768
#define TOK 4096          // B*N = 2*2048
#define SEQ 2048
#define NHEAD 12
#define HDIM 64
#define MLPD 3072

// ---------------- scratch (static device globals; no allocation) ----------------
__device__ float g_xn[TOK * DIM];
__device__ float g_qkv[TOK * 3 * DIM];
__device__ float g_attn[TOK * DIM];
__device__ float g_x1[TOK * DIM];
__device__ float g_h[TOK * DIM];
__device__ float g_h1[TOK * MLPD];
__device__ float g_part[4 * TOK * DIM];   // split-K partials
// pre-rounded (tf32) weights
__device__ float g_wq[DIM * 3 * DIM];
__device__ float g_wp[DIM * DIM];
__device__ float g_w1[DIM * MLPD];
__device__ float g_w2[MLPD * DIM];

// ---------------- tf32 helpers ----------------
__device__ __forceinline__ uint32_t f2tf32(float f) {
    uint32_t u;
    asm("cvt.rna.tf32.f32 %0, %1;" : "=r"(u) : "f"(f));
    return u;
}
__device__ __forceinline__ float rndtf32(float f) { return __uint_as_float(f2tf32(f)); }

__device__ __forceinline__ void mma_tf32(float& c0, float& c1, float& c2, float& c3,
                                         uint32_t a0, uint32_t a1, uint32_t a2, uint32_t a3,
                                         uint32_t b0, uint32_t b1) {
    asm volatile(
        "mma.sync.aligned.m16n8k8.row.col.f32.tf32.tf32.f32 "
        "{%0,%1,%2,%3}, {%4,%5,%6,%7}, {%8,%9}, {%0,%1,%2,%3};"
        : "+f"(c0), "+f"(c1), "+f"(c2), "+f"(c3)
        : "r"(a0), "r"(a1), "r"(a2), "r"(a3), "r"(b0), "r"(b1));
}

// ---------------- weight pre-round: dst = round_tf32(src), 4 elems/thread ----------------
__global__ void round_tf32_kernel(const float* __restrict__ src, float* __restrict__ dst) {
    const int i = (blockIdx.x * 256 + threadIdx.x) * 4;
    float4 v = *(const float4*)&src[i];
    v.x = rndtf32(v.x); v.y = rndtf32(v.y); v.z = rndtf32(v.z); v.w = rndtf32(v.w);
    *(float4*)&dst[i] = v;
}

// ---------------- LayerNorm: one block (256 thr) per row; output tf32-rounded ----------------
__global__ void ln_kernel(const float* __restrict__ x, const float* __restrict__ w,
                          const float* __restrict__ b, float* __restrict__ y) {
    const int row = blockIdx.x;
    const int tid = threadIdx.x;
    const float* xr = x + (size_t)row * DIM;
    float v0 = xr[tid], v1 = xr[tid + 256], v2 = xr[tid + 512];
    float s  = v0 + v1 + v2;
    float sq = v0 * v0 + v1 * v1 + v2 * v2;
    __shared__ float red0[8], red1[8];
    #pragma unroll
    for (int mm = 16; mm; mm >>= 1) {
        s  += __shfl_xor_sync(0xffffffffu, s,  mm);
        sq += __shfl_xor_sync(0xffffffffu, sq, mm);
    }
    const int wid = tid >> 5, lane = tid & 31;
    if (lane == 0) { red0[wid] = s; red1[wid] = sq; }
    __syncthreads();
    if (wid == 0) {
        s = red0[lane & 7]; sq = red1[lane & 7];
        #pragma unroll
        for (int mm = 4; mm; mm >>= 1) {
            s  += __shfl_xor_sync(0xffffffffu, s,  mm);
            sq += __shfl_xor_sync(0xffffffffu, sq, mm);
        }
        if (lane == 0) { red0[0] = s; red1[0] = sq; }
    }
    __syncthreads();
    s = red0[0]; sq = red1[0];
    const float mu  = s * (1.0f / DIM);
    const float var = sq * (1.0f / DIM) - mu * mu;
    const float r   = rsqrtf(var + 1e-5f);
    float* yr = y + (size_t)row * DIM;
    yr[tid]       = rndtf32((v0 - mu) * r * w[tid]       + b[tid]);
    yr[tid + 256] = rndtf32((v1 - mu) * r * w[tid + 256] + b[tid + 256]);
    yr[tid + 512] = rndtf32((v2 - mu) * r * w[tid + 512] + b[tid + 512]);
}

// ---------------- cp.async helpers ----------------
__device__ __forceinline__ void cp16(uint32_t smem_addr, const void* gptr) {
    asm volatile("cp.async.cg.shared.global [%0], [%1], 16;" :: "r"(smem_addr), "l"(gptr));
}
__device__ __forceinline__ void cp_commit() {
    asm volatile("cp.async.commit_group;" ::: "memory");
}
template <int N>
__device__ __forceinline__ void cp_wait() {
    asm volatile("cp.async.wait_group %0;" :: "n"(N) : "memory");
}
__device__ __forceinline__ uint32_t smem_u32(const void* p) {
    uint32_t a;
    asm("{ .reg .u64 t; cvta.to.shared.u64 t, %1; cvt.u32.u64 %0, t; }" : "=r"(a) : "l"(p));
    return a;
}

// ---------------- tf32 GEMM 128x128, BK=16, 4-stage cp.async pipeline ----------------
// Inputs are PRE-ROUNDED to tf32; fragment reads are raw bit loads (no cvt).
// A stage: [128][20] (m, k); B stage: [16][136] (k, n) -- conflict-free reads.
// EPI: 0 = bias (tf32-rounded out), 1 = bias + residual, 2 = bias + GELU (tf32-rounded out), 3 = raw partial
#define AP_STRIDE 20
#define BP_STRIDE 136
#define A_STAGE (128 * AP_STRIDE)
#define B_STAGE (16 * BP_STRIDE)
#define TG_SMEM_BYTES ((4 * A_STAGE + 4 * B_STAGE) * 4)

template <int EPI>
__global__ __launch_bounds__(256, 2)
void tgemm_kernel(const float* __restrict__ A, const float* __restrict__ W,
                  const float* __restrict__ bias, const float* __restrict__ res,
                  float* __restrict__ C, int M, int N, int K, int klen) {
    extern __shared__ float dyn[];
    float* Asm = dyn;
    float* Bsm = dyn + 4 * A_STAGE;

    const int tid = threadIdx.x;
    const int bm = blockIdx.y * 128, bn = blockIdx.x * 128;
    const int z = blockIdx.z;
    A += (size_t)z * klen;
    W += (size_t)z * klen * N;
    if (EPI == 3) C += (size_t)z * M * N;

    const int wid = tid >> 5, lane = tid & 31;
    const int warp_m = wid & 1, warp_n = wid >> 1;       // 2 x 4
    const int g = lane >> 2, tig = lane & 3;

    const int ar = tid >> 2, ac4 = tid & 3;
    const int brr = tid >> 5;
    const int bcg = (tid & 31) * 4;
    const float* ApG  = A + (size_t)(bm + ar) * K + ac4 * 4;
    const float* ApG2 = ApG + (size_t)64 * K;
    const float* BpG  = W + (size_t)brr * N + bn + bcg;
    const float* BpG2 = BpG + (size_t)8 * N;

    const uint32_t sb = smem_u32(dyn);
    const uint32_t adst0 = sb + (ar * AP_STRIDE + ac4 * 4) * 4;
    const uint32_t adst1 = sb + ((ar + 64) * AP_STRIDE + ac4 * 4) * 4;
    const uint32_t bbase = sb + 4 * A_STAGE * 4;
    const uint32_t bdst0 = bbase + (brr * BP_STRIDE + bcg) * 4;
    const uint32_t bdst1 = bbase + ((brr + 8) * BP_STRIDE + bcg) * 4;

    const int nk = klen >> 4;

    auto stage_copy = [&](int s, int ktile) {
        if (ktile < nk) {
            const uint32_t ao = (uint32_t)(s * A_STAGE * 4);
            const uint32_t bo = (uint32_t)(s * B_STAGE * 4);
            cp16(adst0 + ao, ApG  + ktile * 16);
            cp16(adst1 + ao, ApG2 + ktile * 16);
            cp16(bdst0 + bo, BpG  + (size_t)ktile * 16 * N);
            cp16(bdst1 + bo, BpG2 + (size_t)ktile * 16 * N);
        }
        cp_commit();
    };

    float acc[4][4][4];
    #pragma unroll
    for (int i = 0; i < 4; ++i)
        #pragma unroll
        for (int j = 0; j < 4; ++j)
            #pragma unroll
            for (int c = 0; c < 4; ++c) acc[i][j][c] = 0.0f;

    stage_copy(0, 0);
    stage_copy(1, 1);
    stage_copy(2, 2);

    for (int kt = 0; kt < nk; ++kt) {
        cp_wait<2>();
        __syncthreads();

        stage_copy((kt + 3) & 3, kt + 3);

        const float* As = Asm + (kt & 3) * A_STAGE;
        const float* Bs = Bsm + (kt & 3) * B_STAGE;

        #pragma unroll
        for (int ks8 = 0; ks8 < 2; ++ks8) {
            const int ko = ks8 * 8;
            uint32_t bfr[4][2];
            #pragma unroll
            for (int j = 0; j < 4; ++j) {
                const int nb = warp_n * 32 + j * 8 + g;
                bfr[j][0] = __float_as_uint(Bs[(ko + tig) * BP_STRIDE + nb]);
                bfr[j][1] = __float_as_uint(Bs[(ko + tig + 4) * BP_STRIDE + nb]);
            }
            #pragma unroll
            for (int i = 0; i < 4; ++i) {
                const int mb = warp_m * 64 + i * 16;
                const uint32_t a0 = __float_as_uint(As[(mb + g) * AP_STRIDE + ko + tig]);
                const uint32_t a1 = __float_as_uint(As[(mb + g + 8) * AP_STRIDE + ko + tig]);
                const uint32_t a2 = __float_as_uint(As[(mb + g) * AP_STRIDE + ko + tig + 4]);
                const uint32_t a3 = __float_as_uint(As[(mb + g + 8) * AP_STRIDE + ko + tig + 4]);
                #pragma unroll
                for (int j = 0; j < 4; ++j)
                    mma_tf32(acc[i][j][0], acc[i][j][1], acc[i][j][2], acc[i][j][3],
                             a0, a1, a2, a3, bfr[j][0], bfr[j][1]);
            }
        }
    }

    // ---- epilogue
    #pragma unroll
    for (int i = 0; i < 4; ++i) {
        #pragma unroll
        for (int half = 0; half < 2; ++half) {
            const int r = bm + warp_m * 64 + i * 16 + g + half * 8;
            float* Crow = C + (size_t)r * N;
            const float* Rrow = (EPI == 1) ? (res + (size_t)r * N) : nullptr;
            #pragma unroll
            for (int j = 0; j < 4; ++j) {
                const int col = bn + warp_n * 32 + j * 8 + tig * 2;
                float v0 = acc[i][j][half * 2 + 0];
                float v1 = acc[i][j][half * 2 + 1];
                if (EPI != 3) { v0 += bias[col]; v1 += bias[col + 1]; }
                if (EPI == 1) {
                    v0 += Rrow[col];
                    v1 += Rrow[col + 1];
                }
                if (EPI == 2) {
                    v0 = 0.5f * v0 * (1.0f + erff(v0 * 0.70710678118654752f));
                    v1 = 0.5f * v1 * (1.0f + erff(v1 * 0.70710678118654752f));
                }
                if (EPI == 0 || EPI == 2) {   // output is a GEMM/flash operand: pre-round
                    v0 = rndtf32(v0);
                    v1 = rndtf32(v1);
                }
                *(float2*)&Crow[col] = make_float2(v0, v1);
            }
        }
    }
}

// ---------------- split-K combines ----------------
__global__ void combine2_kernel(const float* __restrict__ p, const float* __restrict__ x,
                                const float* __restrict__ bias, float* __restrict__ out) {
    const int i = (blockIdx.x * 256 + threadIdx.x) * 4;
    const int col = i % DIM;
    float4 a = *(const float4*)&p[i];
    float4 b = *(const float4*)&p[(size_t)TOK * DIM + i];
    float4 r = *(const float4*)&x[i];
    float4 bb = *(const float4*)&bias[col];
    float4 o;
    o.x = r.x + bb.x + a.x + b.x;
    o.y = r.y + bb.y + a.y + b.y;
    o.z = r.z + bb.z + a.z + b.z;
    o.w = r.w + bb.w + a.w + b.w;
    *(float4*)&out[i] = o;
}

__global__ void combine4_kernel(const float* __restrict__ p, const float* __restrict__ x1,
                                const float* __restrict__ bias, float* __restrict__ out) {
    const int i = (blockIdx.x * 256 + threadIdx.x) * 4;
    const int col = i % DIM;
    float4 a = *(const float4*)&p[i];
    float4 b = *(const float4*)&p[(size_t)TOK * DIM + i];
    float4 c = *(const float4*)&p[(size_t)2 * TOK * DIM + i];
    float4 d = *(const float4*)&p[(size_t)3 * TOK * DIM + i];
    float4 r = *(const float4*)&x1[i];
    float4 bb = *(const float4*)&bias[col];
    float4 o;
    o.x = r.x + bb.x + ((a.x + b.x) + (c.x + d.x));
    o.y = r.y + bb.y + ((a.y + b.y) + (c.y + d.y));
    o.z = r.z + bb.z + ((a.z + b.z) + (c.z + d.z));
    o.w = r.w + bb.w + ((a.w + b.w) + (c.w + d.w));
    *(float4*)&out[i] = o;
}

// ---------------- tf32 tensor-core flash attention ----------------
// qkv is pre-rounded -> Q/K/V staged as raw uint4 bit-copies. P uses cvt.rna.
// Output (attn) rounded in epilogue (it feeds the proj GEMM).
#define QP 68
#define VP 72
#define FLASH_SMEM_U32 (64 * QP /*Q*/ + 64 * QP /*K=P*/ + 64 * VP /*V*/)

__global__ __launch_bounds__(128, 4)
void flash_tc_kernel(const float* __restrict__ qkv, float* __restrict__ out) {
    extern __shared__ uint32_t sm[];
    uint32_t* Qs = sm;                 // 64 x QP
    uint32_t* Ks = Qs + 64 * QP;       // 64 x QP  (becomes P after S-compute)
    uint32_t* Vs = Ks + 64 * QP;       // 64 x VP
    uint32_t* Ps = Ks;                 // alias

    const int tid = threadIdx.x;
    const int wid = tid >> 5, lane = tid & 31;
    const int g = lane >> 2, tig = lane & 3;
    const int bh = blockIdx.y;
    const int b = bh / NHEAD, h = bh % NHEAD;
    const int q0 = blockIdx.x * 64;
    const int r0 = wid * 16;
    const size_t base = (size_t)b * SEQ * (3 * DIM);

    #pragma unroll
    for (int it = 0; it < 8; ++it) {
        const int f = tid + it * 128;
        const int row = f >> 4, c4 = f & 15;
        *(uint4*)&Qs[row * QP + c4 * 4] =
            *(const uint4*)&qkv[base + (size_t)(q0 + row) * (3 * DIM) + h * 64 + c4 * 4];
    }

    float m0 = -1e30f, m1 = -1e30f, l0 = 0.0f, l1 = 0.0f;
    float oacc[8][4];
    #pragma unroll
    for (int j = 0; j < 8; ++j)
        #pragma unroll
        for (int c = 0; c < 4; ++c) oacc[j][c] = 0.0f;

    for (int kt = 0; kt < SEQ / 64; ++kt) {
        __syncthreads();   // all warps done with P(=Ks) and Vs of previous iter
        #pragma unroll
        for (int it = 0; it < 8; ++it) {
            const int f = tid + it * 128;
            const int row = f >> 4, c4 = f & 15;
            const size_t off = base + (size_t)(kt * 64 + row) * (3 * DIM) + h * 64 + c4 * 4;
            *(uint4*)&Ks[row * QP + c4 * 4] = *(const uint4*)&qkv[off + DIM];
            *(uint4*)&Vs[row * VP + c4 * 4] = *(const uint4*)&qkv[off + 2 * DIM];
        }
        __syncthreads();

        float sacc[8][4];
        #pragma unroll
        for (int j = 0; j < 8; ++j)
            #pragma unroll
            for (int c = 0; c < 4; ++c) sacc[j][c] = 0.0f;

        #pragma unroll
        for (int ks = 0; ks < 64; ks += 8) {
            const uint32_t a0 = Qs[(r0 + g) * QP + ks + tig];
            const uint32_t a1 = Qs[(r0 + g + 8) * QP + ks + tig];
            const uint32_t a2 = Qs[(r0 + g) * QP + ks + tig + 4];
            const uint32_t a3 = Qs[(r0 + g + 8) * QP + ks + tig + 4];
            #pragma unroll
            for (int j = 0; j < 8; ++j) {
                const uint32_t b0 = Ks[(j * 8 + g) * QP + ks + tig];
                const uint32_t b1 = Ks[(j * 8 + g) * QP + ks + tig + 4];
                mma_tf32(sacc[j][0], sacc[j][1], sacc[j][2], sacc[j][3],
                         a0, a1, a2, a3, b0, b1);
            }
        }

        float rm0 = -1e30f, rm1 = -1e30f;
        #pragma unroll
        for (int j = 0; j < 8; ++j) {
            sacc[j][0] *= 0.125f; sacc[j][1] *= 0.125f;
            sacc[j][2] *= 0.125f; sacc[j][3] *= 0.125f;
            rm0 = fmaxf(rm0, fmaxf(sacc[j][0], sacc[j][1]));
            rm1 = fmaxf(rm1, fmaxf(sacc[j][2], sacc[j][3]));
        }
        rm0 = fmaxf(rm0, __shfl_xor_sync(0xffffffffu, rm0, 1));
        rm0 = fmaxf(rm0, __shfl_xor_sync(0xffffffffu, rm0, 2));
        rm1 = fmaxf(rm1, __shfl_xor_sync(0xffffffffu, rm1, 1));
        rm1 = fmaxf(rm1, __shfl_xor_sync(0xffffffffu, rm1, 2));

        const float mn0 = fmaxf(m0, rm0);
        const float mn1 = fmaxf(m1, rm1);
        const float alpha0 = __expf(m0 - mn0);
        const float alpha1 = __expf(m1 - mn1);
        m0 = mn0; m1 = mn1;

        float ps0 = 0.0f, ps1 = 0.0f;
        #pragma unroll
        for (int j = 0; j < 8; ++j) {
            sacc[j][0] = __expf(sacc[j][0] - mn0);
            sacc[j][1] = __expf(sacc[j][1] - mn0);
            sacc[j][2] = __expf(sacc[j][2] - mn1);
            sacc[j][3] = __expf(sacc[j][3] - mn1);
            ps0 += sacc[j][0] + sacc[j][1];
            ps1 += sacc[j][2] + sacc[j][3];
        }
        ps0 += __shfl_xor_sync(0xffffffffu, ps0, 1);
        ps0 += __shfl_xor_sync(0xffffffffu, ps0, 2);
        ps1 += __shfl_xor_sync(0xffffffffu, ps1, 1);
        ps1 += __shfl_xor_sync(0xffffffffu, ps1, 2);
        l0 = l0 * alpha0 + ps0;
        l1 = l1 * alpha1 + ps1;

        #pragma unroll
        for (int j = 0; j < 8; ++j) {
            oacc[j][0] *= alpha0; oacc[j][1] *= alpha0;
            oacc[j][2] *= alpha1; oacc[j][3] *= alpha1;
        }

        __syncthreads();   // all warps finished reading Ks before P overwrites it
        #pragma unroll
        for (int j = 0; j < 8; ++j) {
            const int col = j * 8 + 2 * tig;
            Ps[(r0 + g) * QP + col]         = f2tf32(sacc[j][0]);
            Ps[(r0 + g) * QP + col + 1]     = f2tf32(sacc[j][1]);
            Ps[(r0 + g + 8) * QP + col]     = f2tf32(sacc[j][2]);
            Ps[(r0 + g + 8) * QP + col + 1] = f2tf32(sacc[j][3]);
        }
        __syncwarp();      // P rows are warp-private; warp-local ordering suffices

        #pragma unroll
        for (int ks = 0; ks < 64; ks += 8) {
            const uint32_t a0 = Ps[(r0 + g) * QP + ks + tig];
            const uint32_t a1 = Ps[(r0 + g + 8) * QP + ks + tig];
            const uint32_t a2 = Ps[(r0 + g) * QP + ks + tig + 4];
            const uint32_t a3 = Ps[(r0 + g + 8) * QP + ks + tig + 4];
            #pragma unroll
            for (int j = 0; j < 8; ++j) {
                const uint32_t b0 = Vs[(ks + tig) * VP + j * 8 + g];
                const uint32_t b1 = Vs[(ks + tig + 4) * VP + j * 8 + g];
                mma_tf32(oacc[j][0], oacc[j][1], oacc[j][2], oacc[j][3],
                         a0, a1, a2, a3, b0, b1);
            }
        }
    }

    const float inv0 = 1.0f / l0;
    const float inv1 = 1.0f / l1;
    const int row_g  = b * SEQ + q0 + r0 + g;
    const int row_g8 = row_g + 8;
    #pragma unroll
    for (int j = 0; j < 8; ++j) {
        const int col = h * 64 + j * 8 + 2 * tig;
        *(float2*)&out[(size_t)row_g  * DIM + col] =
            make_float2(rndtf32(oacc[j][0] * inv0), rndtf32(oacc[j][1] * inv0));
        *(float2*)&out[(size_t)row_g8 * DIM + col] =
            make_float2(rndtf32(oacc[j][2] * inv1), rndtf32(oacc[j][3] * inv1));
    }
}

// ---------------- launch ----------------
static float* sym_addr(const void* sym) {
    void* p = nullptr;
    cudaGetSymbolAddress(&p, sym);
    return (float*)p;
}

extern "C" void kernel_launch(void* const* d_in, const int* in_sizes, int n_in,
                              void* d_out, int out_size) {
    const float* x     = (const float*)d_in[0];
    const float* ln1w  = (const float*)d_in[1];
    const float* ln1b  = (const float*)d_in[2];
    const float* qkvw  = (const float*)d_in[3];
    const float* qkvb  = (const float*)d_in[4];
    const float* projw = (const float*)d_in[5];
    const float* projb = (const float*)d_in[6];
    const float* ln2w  = (const float*)d_in[7];
    const float* ln2b  = (const float*)d_in[8];
    const float* lin1w = (const float*)d_in[9];
    const float* lin1b = (const float*)d_in[10];
    const float* lin2w = (const float*)d_in[11];
    const float* lin2b = (const float*)d_in[12];
    float* out = (float*)d_out;

    float* xn   = sym_addr(g_xn);
    float* qkvB = sym_addr(g_qkv);
    float* attn = sym_addr(g_attn);
    float* x1   = sym_addr(g_x1);
    float* hB   = sym_addr(g_h);
    float* h1   = sym_addr(g_h1);
    float* part = sym_addr(g_part);
    float* wq   = sym_addr(g_wq);
    float* wp   = sym_addr(g_wp);
    float* w1   = sym_addr(g_w1);
    float* w2   = sym_addr(g_w2);

    const int flash_smem = FLASH_SMEM_U32 * 4;
    cudaFuncSetAttribute(flash_tc_kernel, cudaFuncAttributeMaxDynamicSharedMemorySize, flash_smem);
    cudaFuncSetAttribute(tgemm_kernel<0>, cudaFuncAttributeMaxDynamicSharedMemorySize, TG_SMEM_BYTES);
    cudaFuncSetAttribute(tgemm_kernel<2>, cudaFuncAttributeMaxDynamicSharedMemorySize, TG_SMEM_BYTES);
    cudaFuncSetAttribute(tgemm_kernel<3>, cudaFuncAttributeMaxDynamicSharedMemorySize, TG_SMEM_BYTES);

    // 0. pre-round weights to tf32 (graph-replayed; ~15us total)
    round_tf32_kernel<<<(DIM * 3 * DIM) / 1024, 256>>>(qkvw, wq);
    round_tf32_kernel<<<(DIM * DIM) / 1024, 256>>>(projw, wp);
    round_tf32_kernel<<<(DIM * MLPD) / 1024, 256>>>(lin1w, w1);
    round_tf32_kernel<<<(MLPD * DIM) / 1024, 256>>>(lin2w, w2);

    // 1. ln1 (tf32-rounded output)
    ln_kernel<<<TOK, 256>>>(x, ln1w, ln1b, xn);
    // 2. qkv = xn @ wq + b (rounded output)
    tgemm_kernel<0><<<dim3(3 * DIM / 128, TOK / 128, 1), 256, TG_SMEM_BYTES>>>(
        xn, wq, qkvb, nullptr, qkvB, TOK, 3 * DIM, DIM, DIM);
    // 3. attention (rounded output)
    flash_tc_kernel<<<dim3(SEQ / 64, 2 * NHEAD), 128, flash_smem>>>(qkvB, attn);
    // 4a. proj partials (split-K=2)
    tgemm_kernel<3><<<dim3(DIM / 128, TOK / 128, 2), 256, TG_SMEM_BYTES>>>(
        attn, wp, nullptr, nullptr, part, TOK, DIM, DIM, DIM / 2);
    // 4b. x1 = x + proj_b + p0 + p1
    combine2_kernel<<<(TOK * DIM / 4) / 256, 256>>>(part, x, projb, x1);
    // 5. ln2 (rounded output)
    ln_kernel<<<TOK, 256>>>(x1, ln2w, ln2b, hB);
    // 6. h1 = gelu(hB @ w1 + b) (rounded output)
    tgemm_kernel<2><<<dim3(MLPD / 128, TOK / 128, 1), 256, TG_SMEM_BYTES>>>(
        hB, w1, lin1b, nullptr, h1, TOK, MLPD, DIM, DIM);
    // 7a. lin2 partials (split-K=4)
    tgemm_kernel<3><<<dim3(DIM / 128, TOK / 128, 4), 256, TG_SMEM_BYTES>>>(
        h1, w2, nullptr, nullptr, part, TOK, DIM, MLPD, MLPD / 4);
    // 7b. out = x1 + lin2_b + sum partials
    combine4_kernel<<<(TOK * DIM / 4) / 256, 256>>>(part, x1, lin2b, out);
}

// round 15
// speedup vs baseline: 1.0452x; 1.0253x over previous
#include <cuda_runtime.h>
#include <math.h>
#include <stdint.h>

#define DIM 768
#define TOK 4096          // B*N = 2*2048
#define SEQ 2048
#define NHEAD 12
#define HDIM 64
#define MLPD 3072

// ---------------- scratch (static device globals; no allocation) ----------------
__device__ float g_xn[TOK * DIM];
__device__ float g_qkv[TOK * 3 * DIM];
__device__ float g_attn[TOK * DIM];
__device__ float g_x1[TOK * DIM];
__device__ float g_h[TOK * DIM];
__device__ float g_h1[TOK * MLPD];
__device__ float g_part[4 * TOK * DIM];   // split-K partials (proj and lin2, 4 each)
// pre-rounded (tf32) weights
__device__ float g_wq[DIM * 3 * DIM];
__device__ float g_wp[DIM * DIM];
__device__ float g_w1[DIM * MLPD];
__device__ float g_w2[MLPD * DIM];

// ---------------- tf32 helpers ----------------
__device__ __forceinline__ uint32_t f2tf32(float f) {
    uint32_t u;
    asm("cvt.rna.tf32.f32 %0, %1;" : "=r"(u) : "f"(f));
    return u;
}
__device__ __forceinline__ float rndtf32(float f) { return __uint_as_float(f2tf32(f)); }

__device__ __forceinline__ void mma_tf32(float& c0, float& c1, float& c2, float& c3,
                                         uint32_t a0, uint32_t a1, uint32_t a2, uint32_t a3,
                                         uint32_t b0, uint32_t b1) {
    asm volatile(
        "mma.sync.aligned.m16n8k8.row.col.f32.tf32.tf32.f32 "
        "{%0,%1,%2,%3}, {%4,%5,%6,%7}, {%8,%9}, {%0,%1,%2,%3};"
        : "+f"(c0), "+f"(c1), "+f"(c2), "+f"(c3)
        : "r"(a0), "r"(a1), "r"(a2), "r"(a3), "r"(b0), "r"(b1));
}

// ---------------- merged weight pre-round (all 4 weight matrices, 1 launch) ----------------
#define S1 (DIM * 3 * DIM)            // 1769472
#define S2 (DIM * DIM)                // 589824
#define S3 (DIM * MLPD)               // 2359296
#define WTOT (S1 + S2 + S3 + S3)      // 7077888
__global__ void round_all_kernel(const float* __restrict__ qkvw, const float* __restrict__ projw,
                                 const float* __restrict__ lin1w, const float* __restrict__ lin2w,
                                 float* __restrict__ wq, float* __restrict__ wp,
                                 float* __restrict__ w1, float* __restrict__ w2) {
    const int i = (blockIdx.x * 256 + threadIdx.x) * 4;
    const float* src; float* dst; int off;
    if (i < S1)                { src = qkvw;  dst = wq; off = i; }
    else if (i < S1 + S2)      { src = projw; dst = wp; off = i - S1; }
    else if (i < S1 + S2 + S3) { src = lin1w; dst = w1; off = i - S1 - S2; }
    else                       { src = lin2w; dst = w2; off = i - S1 - S2 - S3; }
    float4 v = *(const float4*)&src[off];
    v.x = rndtf32(v.x); v.y = rndtf32(v.y); v.z = rndtf32(v.z); v.w = rndtf32(v.w);
    *(float4*)&dst[off] = v;
}

// ---------------- LayerNorm: one block (256 thr) per row; output tf32-rounded ----------------
__global__ void ln_kernel(const float* __restrict__ x, const float* __restrict__ w,
                          const float* __restrict__ b, float* __restrict__ y) {
    const int row = blockIdx.x;
    const int tid = threadIdx.x;
    const float* xr = x + (size_t)row * DIM;
    float v0 = xr[tid], v1 = xr[tid + 256], v2 = xr[tid + 512];
    float s  = v0 + v1 + v2;
    float sq = v0 * v0 + v1 * v1 + v2 * v2;
    __shared__ float red0[8], red1[8];
    #pragma unroll
    for (int mm = 16; mm; mm >>= 1) {
        s  += __shfl_xor_sync(0xffffffffu, s,  mm);
        sq += __shfl_xor_sync(0xffffffffu, sq, mm);
    }
    const int wid = tid >> 5, lane = tid & 31;
    if (lane == 0) { red0[wid] = s; red1[wid] = sq; }
    __syncthreads();
    if (wid == 0) {
        s = red0[lane & 7]; sq = red1[lane & 7];
        #pragma unroll
        for (int mm = 4; mm; mm >>= 1) {
            s  += __shfl_xor_sync(0xffffffffu, s,  mm);
            sq += __shfl_xor_sync(0xffffffffu, sq, mm);
        }
        if (lane == 0) { red0[0] = s; red1[0] = sq; }
    }
    __syncthreads();
    s = red0[0]; sq = red1[0];
    const float mu  = s * (1.0f / DIM);
    const float var = sq * (1.0f / DIM) - mu * mu;
    const float r   = rsqrtf(var + 1e-5f);
    float* yr = y + (size_t)row * DIM;
    yr[tid]       = rndtf32((v0 - mu) * r * w[tid]       + b[tid]);
    yr[tid + 256] = rndtf32((v1 - mu) * r * w[tid + 256] + b[tid + 256]);
    yr[tid + 512] = rndtf32((v2 - mu) * r * w[tid + 512] + b[tid + 512]);
}

// ---------------- cp.async helpers ----------------
__device__ __forceinline__ void cp16(uint32_t smem_addr, const void* gptr) {
    asm volatile("cp.async.cg.shared.global [%0], [%1], 16;" :: "r"(smem_addr), "l"(gptr));
}
__device__ __forceinline__ void cp_commit() {
    asm volatile("cp.async.commit_group;" ::: "memory");
}
template <int N>
__device__ __forceinline__ void cp_wait() {
    asm volatile("cp.async.wait_group %0;" :: "n"(N) : "memory");
}
__device__ __forceinline__ uint32_t smem_u32(const void* p) {
    uint32_t a;
    asm("{ .reg .u64 t; cvta.to.shared.u64 t, %1; cvt.u32.u64 %0, t; }" : "=r"(a) : "l"(p));
    return a;
}

// ---------------- tf32 GEMM 128x256, BK=16, 4-stage cp.async, warp tile 64x64 ----------------
// Inputs PRE-ROUNDED to tf32; fragment reads are raw bit loads.
// A stage: [128][20] (m, k) -- reads 20g+tig distinct mod 32.
// B stage: [16][264] (k, n) -- 264 mod 32 = 8 -> reads 8*tig+g distinct mod 32.
// EPI: 0 = bias (tf32-rounded out), 2 = bias + GELU (rounded out), 3 = raw partial
#define AP_STRIDE 20
#define BP_STRIDE 264
#define A_STAGE (128 * AP_STRIDE)            // 2560 floats
#define B_STAGE (16 * BP_STRIDE)             // 4224 floats
#define TG_SMEM_BYTES ((4 * A_STAGE + 4 * B_STAGE) * 4)   // 108544

template <int EPI>
__global__ __launch_bounds__(256, 1)
void tgemm_kernel(const float* __restrict__ A, const float* __restrict__ W,
                  const float* __restrict__ bias, const float* __restrict__ res,
                  float* __restrict__ C, int M, int N, int K, int klen) {
    extern __shared__ float dyn[];
    float* Asm = dyn;
    float* Bsm = dyn + 4 * A_STAGE;

    const int tid = threadIdx.x;
    const int bm = blockIdx.y * 128, bn = blockIdx.x * 256;
    const int z = blockIdx.z;
    A += (size_t)z * klen;
    W += (size_t)z * klen * N;
    if (EPI == 3) C += (size_t)z * M * N;

    const int wid = tid >> 5, lane = tid & 31;
    const int warp_m = wid & 1, warp_n = wid >> 1;       // 2 x 4, warp tile 64x64
    const int g = lane >> 2, tig = lane & 3;

    // global copy coverage: A 2x16B/thread, B 4x16B/thread per stage
    const int ar = tid >> 2, ac4 = tid & 3;              // A rows ar, ar+64; k-off ac4*4
    const int brr = tid >> 6;                             // B base k-row (0..3); rows brr+4e
    const int bcg = (tid & 63) * 4;                       // B n-cols bcg..+3
    const float* ApG  = A + (size_t)(bm + ar) * K + ac4 * 4;
    const float* ApG2 = ApG + (size_t)64 * K;
    const float* BpG[4] = {
        W + (size_t)(brr)      * N + bn + bcg,
        W + (size_t)(brr + 4)  * N + bn + bcg,
        W + (size_t)(brr + 8)  * N + bn + bcg,
        W + (size_t)(brr + 12) * N + bn + bcg };

    const uint32_t sb = smem_u32(dyn);
    const uint32_t adst0 = sb + (ar * AP_STRIDE + ac4 * 4) * 4;
    const uint32_t adst1 = sb + ((ar + 64) * AP_STRIDE + ac4 * 4) * 4;
    const uint32_t bbase = sb + 4 * A_STAGE * 4;
    uint32_t bdst[4];
    #pragma unroll
    for (int e = 0; e < 4; ++e)
        bdst[e] = bbase + ((brr + 4 * e) * BP_STRIDE + bcg) * 4;

    const int nk = klen >> 4;

    auto stage_copy = [&](int s, int ktile) {
        if (ktile < nk) {
            const uint32_t ao = (uint32_t)(s * A_STAGE * 4);
            const uint32_t bo = (uint32_t)(s * B_STAGE * 4);
            cp16(adst0 + ao, ApG  + ktile * 16);
            cp16(adst1 + ao, ApG2 + ktile * 16);
            const size_t koff = (size_t)ktile * 16 * N;
            #pragma unroll
            for (int e = 0; e < 4; ++e)
                cp16(bdst[e] + bo, BpG[e] + koff);
        }
        cp_commit();
    };

    float acc[4][8][4];
    #pragma unroll
    for (int i = 0; i < 4; ++i)
        #pragma unroll
        for (int j = 0; j < 8; ++j)
            #pragma unroll
            for (int c = 0; c < 4; ++c) acc[i][j][c] = 0.0f;

    stage_copy(0, 0);
    stage_copy(1, 1);
    stage_copy(2, 2);

    for (int kt = 0; kt < nk; ++kt) {
        cp_wait<2>();
        __syncthreads();

        stage_copy((kt + 3) & 3, kt + 3);

        const float* As = Asm + (kt & 3) * A_STAGE;
        const float* Bs = Bsm + (kt & 3) * B_STAGE;

        #pragma unroll
        for (int ks8 = 0; ks8 < 2; ++ks8) {
            const int ko = ks8 * 8;
            uint32_t bfr[8][2];
            #pragma unroll
            for (int j = 0; j < 8; ++j) {
                const int nb = warp_n * 64 + j * 8 + g;
                bfr[j][0] = __float_as_uint(Bs[(ko + tig) * BP_STRIDE + nb]);
                bfr[j][1] = __float_as_uint(Bs[(ko + tig + 4) * BP_STRIDE + nb]);
            }
            #pragma unroll
            for (int i = 0; i < 4; ++i) {
                const int mb = warp_m * 64 + i * 16;
                const uint32_t a0 = __float_as_uint(As[(mb + g) * AP_STRIDE + ko + tig]);
                const uint32_t a1 = __float_as_uint(As[(mb + g + 8) * AP_STRIDE + ko + tig]);
                const uint32_t a2 = __float_as_uint(As[(mb + g) * AP_STRIDE + ko + tig + 4]);
                const uint32_t a3 = __float_as_uint(As[(mb + g + 8) * AP_STRIDE + ko + tig + 4]);
                #pragma unroll
                for (int j = 0; j < 8; ++j)
                    mma_tf32(acc[i][j][0], acc[i][j][1], acc[i][j][2], acc[i][j][3],
                             a0, a1, a2, a3, bfr[j][0], bfr[j][1]);
            }
        }
    }

    // ---- epilogue: thread owns rows {g, g+8} per m-tile, col pair 2*tig per n-tile
    #pragma unroll
    for (int i = 0; i < 4; ++i) {
        #pragma unroll
        for (int half = 0; half < 2; ++half) {
            const int r = bm + warp_m * 64 + i * 16 + g + half * 8;
            float* Crow = C + (size_t)r * N;
            #pragma unroll
            for (int j = 0; j < 8; ++j) {
                const int col = bn + warp_n * 64 + j * 8 + tig * 2;
                float v0 = acc[i][j][half * 2 + 0];
                float v1 = acc[i][j][half * 2 + 1];
                if (EPI != 3) { v0 += bias[col]; v1 += bias[col + 1]; }
                if (EPI == 2) {
                    v0 = 0.5f * v0 * (1.0f + erff(v0 * 0.70710678118654752f));
                    v1 = 0.5f * v1 * (1.0f + erff(v1 * 0.70710678118654752f));
                }
                if (EPI == 0 || EPI == 2) {   // output feeds another tf32 MMA: pre-round
                    v0 = rndtf32(v0);
                    v1 = rndtf32(v1);
                }
                *(float2*)&Crow[col] = make_float2(v0, v1);
            }
        }
    }
}

// ---------------- split-K combine: out = res + bias + sum of 4 partials ----------------
__global__ void combine4_kernel(const float* __restrict__ p, const float* __restrict__ res,
                                const float* __restrict__ bias, float* __restrict__ out) {
    const int i = (blockIdx.x * 256 + threadIdx.x) * 4;
    const int col = i % DIM;
    float4 a = *(const float4*)&p[i];
    float4 b = *(const float4*)&p[(size_t)TOK * DIM + i];
    float4 c = *(const float4*)&p[(size_t)2 * TOK * DIM + i];
    float4 d = *(const float4*)&p[(size_t)3 * TOK * DIM + i];
    float4 r = *(const float4*)&res[i];
    float4 bb = *(const float4*)&bias[col];
    float4 o;
    o.x = r.x + bb.x + ((a.x + b.x) + (c.x + d.x));
    o.y = r.y + bb.y + ((a.y + b.y) + (c.y + d.y));
    o.z = r.z + bb.z + ((a.z + b.z) + (c.z + d.z));
    o.w = r.w + bb.w + ((a.w + b.w) + (c.w + d.w));
    *(float4*)&out[i] = o;
}

// ---------------- tf32 tensor-core flash attention (unchanged) ----------------
#define QP 68
#define VP 72
#define FLASH_SMEM_U32 (64 * QP /*Q*/ + 64 * QP /*K=P*/ + 64 * VP /*V*/)

__global__ __launch_bounds__(128, 4)
void flash_tc_kernel(const float* __restrict__ qkv, float* __restrict__ out) {
    extern __shared__ uint32_t sm[];
    uint32_t* Qs = sm;
    uint32_t* Ks = Qs + 64 * QP;
    uint32_t* Vs = Ks + 64 * QP;
    uint32_t* Ps = Ks;                 // alias

    const int tid = threadIdx.x;
    const int wid = tid >> 5, lane = tid & 31;
    const int g = lane >> 2, tig = lane & 3;
    const int bh = blockIdx.y;
    const int b = bh / NHEAD, h = bh % NHEAD;
    const int q0 = blockIdx.x * 64;
    const int r0 = wid * 16;
    const size_t base = (size_t)b * SEQ * (3 * DIM);

    #pragma unroll
    for (int it = 0; it < 8; ++it) {
        const int f = tid + it * 128;
        const int row = f >> 4, c4 = f & 15;
        *(uint4*)&Qs[row * QP + c4 * 4] =
            *(const uint4*)&qkv[base + (size_t)(q0 + row) * (3 * DIM) + h * 64 + c4 * 4];
    }

    float m0 = -1e30f, m1 = -1e30f, l0 = 0.0f, l1 = 0.0f;
    float oacc[8][4];
    #pragma unroll
    for (int j = 0; j < 8; ++j)
        #pragma unroll
        for (int c = 0; c < 4; ++c) oacc[j][c] = 0.0f;

    for (int kt = 0; kt < SEQ / 64; ++kt) {
        __syncthreads();
        #pragma unroll
        for (int it = 0; it < 8; ++it) {
            const int f = tid + it * 128;
            const int row = f >> 4, c4 = f & 15;
            const size_t off = base + (size_t)(kt * 64 + row) * (3 * DIM) + h * 64 + c4 * 4;
            *(uint4*)&Ks[row * QP + c4 * 4] = *(const uint4*)&qkv[off + DIM];
            *(uint4*)&Vs[row * VP + c4 * 4] = *(const uint4*)&qkv[off + 2 * DIM];
        }
        __syncthreads();

        float sacc[8][4];
        #pragma unroll
        for (int j = 0; j < 8; ++j)
            #pragma unroll
            for (int c = 0; c < 4; ++c) sacc[j][c] = 0.0f;

        #pragma unroll
        for (int ks = 0; ks < 64; ks += 8) {
            const uint32_t a0 = Qs[(r0 + g) * QP + ks + tig];
            const uint32_t a1 = Qs[(r0 + g + 8) * QP + ks + tig];
            const uint32_t a2 = Qs[(r0 + g) * QP + ks + tig + 4];
            const uint32_t a3 = Qs[(r0 + g + 8) * QP + ks + tig + 4];
            #pragma unroll
            for (int j = 0; j < 8; ++j) {
                const uint32_t b0 = Ks[(j * 8 + g) * QP + ks + tig];
                const uint32_t b1 = Ks[(j * 8 + g) * QP + ks + tig + 4];
                mma_tf32(sacc[j][0], sacc[j][1], sacc[j][2], sacc[j][3],
                         a0, a1, a2, a3, b0, b1);
            }
        }

        float rm0 = -1e30f, rm1 = -1e30f;
        #pragma unroll
        for (int j = 0; j < 8; ++j) {
            sacc[j][0] *= 0.125f; sacc[j][1] *= 0.125f;
            sacc[j][2] *= 0.125f; sacc[j][3] *= 0.125f;
            rm0 = fmaxf(rm0, fmaxf(sacc[j][0], sacc[j][1]));
            rm1 = fmaxf(rm1, fmaxf(sacc[j][2], sacc[j][3]));
        }
        rm0 = fmaxf(rm0, __shfl_xor_sync(0xffffffffu, rm0, 1));
        rm0 = fmaxf(rm0, __shfl_xor_sync(0xffffffffu, rm0, 2));
        rm1 = fmaxf(rm1, __shfl_xor_sync(0xffffffffu, rm1, 1));
        rm1 = fmaxf(rm1, __shfl_xor_sync(0xffffffffu, rm1, 2));

        const float mn0 = fmaxf(m0, rm0);
        const float mn1 = fmaxf(m1, rm1);
        const float alpha0 = __expf(m0 - mn0);
        const float alpha1 = __expf(m1 - mn1);
        m0 = mn0; m1 = mn1;

        float ps0 = 0.0f, ps1 = 0.0f;
        #pragma unroll
        for (int j = 0; j < 8; ++j) {
            sacc[j][0] = __expf(sacc[j][0] - mn0);
            sacc[j][1] = __expf(sacc[j][1] - mn0);
            sacc[j][2] = __expf(sacc[j][2] - mn1);
            sacc[j][3] = __expf(sacc[j][3] - mn1);
            ps0 += sacc[j][0] + sacc[j][1];
            ps1 += sacc[j][2] + sacc[j][3];
        }
        ps0 += __shfl_xor_sync(0xffffffffu, ps0, 1);
        ps0 += __shfl_xor_sync(0xffffffffu, ps0, 2);
        ps1 += __shfl_xor_sync(0xffffffffu, ps1, 1);
        ps1 += __shfl_xor_sync(0xffffffffu, ps1, 2);
        l0 = l0 * alpha0 + ps0;
        l1 = l1 * alpha1 + ps1;

        #pragma unroll
        for (int j = 0; j < 8; ++j) {
            oacc[j][0] *= alpha0; oacc[j][1] *= alpha0;
            oacc[j][2] *= alpha1; oacc[j][3] *= alpha1;
        }

        __syncthreads();
        #pragma unroll
        for (int j = 0; j < 8; ++j) {
            const int col = j * 8 + 2 * tig;
            Ps[(r0 + g) * QP + col]         = f2tf32(sacc[j][0]);
            Ps[(r0 + g) * QP + col + 1]     = f2tf32(sacc[j][1]);
            Ps[(r0 + g + 8) * QP + col]     = f2tf32(sacc[j][2]);
            Ps[(r0 + g + 8) * QP + col + 1] = f2tf32(sacc[j][3]);
        }
        __syncwarp();

        #pragma unroll
        for (int ks = 0; ks < 64; ks += 8) {
            const uint32_t a0 = Ps[(r0 + g) * QP + ks + tig];
            const uint32_t a1 = Ps[(r0 + g + 8) * QP + ks + tig];
            const uint32_t a2 = Ps[(r0 + g) * QP + ks + tig + 4];
            const uint32_t a3 = Ps[(r0 + g + 8) * QP + ks + tig + 4];
            #pragma unroll
            for (int j = 0; j < 8; ++j) {
                const uint32_t b0 = Vs[(ks + tig) * VP + j * 8 + g];
                const uint32_t b1 = Vs[(ks + tig + 4) * VP + j * 8 + g];
                mma_tf32(oacc[j][0], oacc[j][1], oacc[j][2], oacc[j][3],
                         a0, a1, a2, a3, b0, b1);
            }
        }
    }

    const float inv0 = 1.0f / l0;
    const float inv1 = 1.0f / l1;
    const int row_g  = b * SEQ + q0 + r0 + g;
    const int row_g8 = row_g + 8;
    #pragma unroll
    for (int j = 0; j < 8; ++j) {
        const int col = h * 64 + j * 8 + 2 * tig;
        *(float2*)&out[(size_t)row_g  * DIM + col] =
            make_float2(rndtf32(oacc[j][0] * inv0), rndtf32(oacc[j][1] * inv0));
        *(float2*)&out[(size_t)row_g8 * DIM + col] =
            make_float2(rndtf32(oacc[j][2] * inv1), rndtf32(oacc[j][3] * inv1));
    }
}

// ---------------- launch ----------------
static float* sym_addr(const void* sym) {
    void* p = nullptr;
    cudaGetSymbolAddress(&p, sym);
    return (float*)p;
}

extern "C" void kernel_launch(void* const* d_in, const int* in_sizes, int n_in,
                              void* d_out, int out_size) {
    const float* x     = (const float*)d_in[0];
    const float* ln1w  = (const float*)d_in[1];
    const float* ln1b  = (const float*)d_in[2];
    const float* qkvw  = (const float*)d_in[3];
    const float* qkvb  = (const float*)d_in[4];
    const float* projw = (const float*)d_in[5];
    const float* projb = (const float*)d_in[6];
    const float* ln2w  = (const float*)d_in[7];
    const float* ln2b  = (const float*)d_in[8];
    const float* lin1w = (const float*)d_in[9];
    const float* lin1b = (const float*)d_in[10];
    const float* lin2w = (const float*)d_in[11];
    const float* lin2b = (const float*)d_in[12];
    float* out = (float*)d_out;

    float* xn   = sym_addr(g_xn);
    float* qkvB = sym_addr(g_qkv);
    float* attn = sym_addr(g_attn);
    float* x1   = sym_addr(g_x1);
    float* hB   = sym_addr(g_h);
    float* h1   = sym_addr(g_h1);
    float* part = sym_addr(g_part);
    float* wq   = sym_addr(g_wq);
    float* wp   = sym_addr(g_wp);
    float* w1   = sym_addr(g_w1);
    float* w2   = sym_addr(g_w2);

    const int flash_smem = FLASH_SMEM_U32 * 4;
    cudaFuncSetAttribute(flash_tc_kernel, cudaFuncAttributeMaxDynamicSharedMemorySize, flash_smem);
    cudaFuncSetAttribute(tgemm_kernel<0>, cudaFuncAttributeMaxDynamicSharedMemorySize, TG_SMEM_BYTES);
    cudaFuncSetAttribute(tgemm_kernel<2>, cudaFuncAttributeMaxDynamicSharedMemorySize, TG_SMEM_BYTES);
    cudaFuncSetAttribute(tgemm_kernel<3>, cudaFuncAttributeMaxDynamicSharedMemorySize, TG_SMEM_BYTES);

    // 0. pre-round all weights to tf32 (one launch)
    round_all_kernel<<<WTOT / 1024, 256>>>(qkvw, projw, lin1w, lin2w, wq, wp, w1, w2);

    // 1. ln1 (tf32-rounded output)
    ln_kernel<<<TOK, 256>>>(x, ln1w, ln1b, xn);
    // 2. qkv = xn @ wq + b  (128x256 tiles: grid 9 x 32)
    tgemm_kernel<0><<<dim3(3 * DIM / 256, TOK / 128, 1), 256, TG_SMEM_BYTES>>>(
        xn, wq, qkvb, nullptr, qkvB, TOK, 3 * DIM, DIM, DIM);
    // 3. attention
    flash_tc_kernel<<<dim3(SEQ / 64, 2 * NHEAD), 128, flash_smem>>>(qkvB, attn);
    // 4a. proj partials (split-K=4: grid 3 x 32 x 4, klen=192)
    tgemm_kernel<3><<<dim3(DIM / 256, TOK / 128, 4), 256, TG_SMEM_BYTES>>>(
        attn, wp, nullptr, nullptr, part, TOK, DIM, DIM, DIM / 4);
    // 4b. x1 = x + proj_b + sum partials
    combine4_kernel<<<(TOK * DIM / 4) / 256, 256>>>(part, x, projb, x1);
    // 5. ln2 (rounded output)
    ln_kernel<<<TOK, 256>>>(x1, ln2w, ln2b, hB);
    // 6. h1 = gelu(hB @ w1 + b)  (grid 12 x 32)
    tgemm_kernel<2><<<dim3(MLPD / 256, TOK / 128, 1), 256, TG_SMEM_BYTES>>>(
        hB, w1, lin1b, nullptr, h1, TOK, MLPD, DIM, DIM);
    // 7a. lin2 partials (split-K=4: grid 3 x 32 x 4, klen=768)
    tgemm_kernel<3><<<dim3(DIM / 256, TOK / 128, 4), 256, TG_SMEM_BYTES>>>(
        h1, w2, nullptr, nullptr, part, TOK, DIM, MLPD, MLPD / 4);
    // 7b. out = x1 + lin2_b + sum partials
    combine4_kernel<<<(TOK * DIM / 4) / 256, 256>>>(part, x1, lin2b, out);
}